// round 13
// baseline (speedup 1.0000x reference)
#include <cuda_runtime.h>
#include <cstdint>

#define B_   64
#define A_   1024
#define D_   5
#define F_   256
#define NB_  6
#define O_   256
#define K_   262
#define TM   64
#define NTHR 320          // 256 consumers + 64 producers
#define NCONS 256
#define CHK  32
#define NC   9            // 8 atom chunks of 32 + 1 bonds chunk of 6
#define NBUF 4
#define ROWS_TOTAL (B_ * A_)
#define NTILES (ROWS_TOTAL / TM)
#define WSTRIDE (K_ * O_)

typedef unsigned long long ull;

__device__ int g_cnt[8];          // statically zero; reset by last CTA each call
__device__ int g_done;
__device__ int g_lists[6][ROWS_TOTAL];

__device__ __forceinline__ ull pack2(float x) {
    ull r; asm("mov.b64 %0, {%1, %1};" : "=l"(r) : "f"(x)); return r;
}
__device__ __forceinline__ void fma2(ull& a, ull x, ull y) {
    asm("fma.rn.f32x2 %0, %1, %2, %0;" : "+l"(a) : "l"(x), "l"(y));
}
__device__ __forceinline__ float sigf(float z) {
    return __fdividef(1.f, 1.f + __expf(-z));
}
#define BAR_SYNC(id)   asm volatile("bar.sync %0, %1;"   :: "r"(id), "r"(NTHR) : "memory")
#define BAR_ARRIVE(id) asm volatile("bar.arrive %0, %1;" :: "r"(id), "r"(NTHR) : "memory")

__global__ void classify_kernel(const int* __restrict__ edges) {
    int rid = blockIdx.x * blockDim.x + threadIdx.x;
    const int* e = edges + (size_t)rid * D_;
    int d = 0;
    #pragma unroll
    for (int j = 0; j < D_; j++) d += (e[j] >= 0);
    unsigned lt = (1u << (threadIdx.x & 31)) - 1u;
    #pragma unroll
    for (int dd = 0; dd < 6; dd++) {
        unsigned m = __ballot_sync(0xffffffffu, d == dd);
        if (d == dd) {
            int leader = __ffs(m) - 1;
            int base = 0;
            if ((int)(threadIdx.x & 31) == leader) base = atomicAdd(&g_cnt[dd], __popc(m));
            base = __shfl_sync(m, base, leader);
            g_lists[dd][base + __popc(m & lt)] = rid;
        }
    }
}

// ---- producer: build one chunk (8 jobs per producer thread) ----
__device__ __forceinline__ void build_chunk_prod(float* __restrict__ dst, int c, int ptid,
                                                 const float* __restrict__ atoms,
                                                 const float* __restrict__ bonds,
                                                 const int* __restrict__ rid_s,
                                                 const int* __restrict__ edg_s) {
    if (c < 8) {
        const float4* a4 = (const float4*)atoms;
        #pragma unroll
        for (int jt = 0; jt < 8; jt++) {
            int job = jt * 64 + ptid;
            int r = job >> 3, c4 = job & 7;
            int rid = rid_s[r];
            int cg = c * 8 + c4;
            float4 v = a4[(size_t)rid * 64 + cg];
            int bbase = rid & ~(A_ - 1);
            #pragma unroll
            for (int j = 0; j < D_; j++) {
                int e = edg_s[r * D_ + j];
                if (e >= 0) {
                    float4 n = a4[(size_t)(bbase + e) * 64 + cg];
                    v.x += n.x; v.y += n.y; v.z += n.z; v.w += n.w;
                }
            }
            int p = (r >> 2) ^ c4;
            float* b = dst + (4 * c4) * 64 + 4 * p + (r & 3);
            b[0 * 64] = v.x;
            b[1 * 64] = v.y;
            b[2 * 64] = v.z;
            b[3 * 64] = v.w;
        }
    } else {
        #pragma unroll
        for (int jt = 0; jt < 8; jt++) {
            int job = jt * 64 + ptid;
            int r = job >> 3, c4 = job & 7;
            if (c4 < 2) {
                const float* bb = bonds + (size_t)rid_s[r] * (D_ * NB_);
                #pragma unroll
                for (int q = 0; q < 4; q++) {
                    int nb = 4 * c4 + q;
                    if (nb < NB_) {
                        float s = 0.f;
                        #pragma unroll
                        for (int j = 0; j < D_; j++) s += bb[j * NB_ + nb];
                        int p = (r >> 2) ^ (nb >> 2);
                        dst[nb * 64 + 4 * p + (r & 3)] = s;
                    }
                }
            }
        }
    }
}

// ---- consumer GEMV over one chunk: 16 rows x 4 cols per thread (R5 rolled form) ----
template <int NK>
__device__ __forceinline__ void gemv_chunk(const float* __restrict__ fb,
                                           const float* __restrict__ wk,
                                           int h, ull acc[8][4]) {
    #pragma unroll
    for (int k4 = 0; k4 < (NK + 3) / 4; k4++) {
        const int sk = k4;
        int of0 = 4 * ((4 * h + 0) ^ sk);
        int of1 = 4 * ((4 * h + 1) ^ sk);
        int of2 = 4 * ((4 * h + 2) ^ sk);
        int of3 = 4 * ((4 * h + 3) ^ sk);
        const float* f0 = fb + k4 * 4 * 64;
        const int jmax = (NK - 4 * k4 < 4) ? (NK - 4 * k4) : 4;
        #pragma unroll
        for (int j = 0; j < jmax; j++) {
            float4 w = *(const float4*)(wk + (size_t)(4 * k4 + j) * O_);
            ull wx = pack2(w.x), wy = pack2(w.y), wz = pack2(w.z), ww = pack2(w.w);
            const float* fj = f0 + j * 64;
            ulonglong2 fa = *(const ulonglong2*)(fj + of0);
            ulonglong2 fb2 = *(const ulonglong2*)(fj + of1);
            ulonglong2 fc = *(const ulonglong2*)(fj + of2);
            ulonglong2 fd = *(const ulonglong2*)(fj + of3);
            fma2(acc[0][0], fa.x, wx); fma2(acc[0][1], fa.x, wy); fma2(acc[0][2], fa.x, wz); fma2(acc[0][3], fa.x, ww);
            fma2(acc[1][0], fa.y, wx); fma2(acc[1][1], fa.y, wy); fma2(acc[1][2], fa.y, wz); fma2(acc[1][3], fa.y, ww);
            fma2(acc[2][0], fb2.x, wx); fma2(acc[2][1], fb2.x, wy); fma2(acc[2][2], fb2.x, wz); fma2(acc[2][3], fb2.x, ww);
            fma2(acc[3][0], fb2.y, wx); fma2(acc[3][1], fb2.y, wy); fma2(acc[3][2], fb2.y, wz); fma2(acc[3][3], fb2.y, ww);
            fma2(acc[4][0], fc.x, wx); fma2(acc[4][1], fc.x, wy); fma2(acc[4][2], fc.x, wz); fma2(acc[4][3], fc.x, ww);
            fma2(acc[5][0], fc.y, wx); fma2(acc[5][1], fc.y, wy); fma2(acc[5][2], fc.y, wz); fma2(acc[5][3], fc.y, ww);
            fma2(acc[6][0], fd.x, wx); fma2(acc[6][1], fd.x, wy); fma2(acc[6][2], fd.x, wz); fma2(acc[6][3], fd.x, ww);
            fma2(acc[7][0], fd.y, wx); fma2(acc[7][1], fd.y, wy); fma2(acc[7][2], fd.y, wz); fma2(acc[7][3], fd.y, ww);
        }
    }
}

__global__ void __launch_bounds__(NTHR, 1)
nfp_gemm(const float* __restrict__ atoms,
         const float* __restrict__ bonds,
         const int*   __restrict__ edges,
         const float* __restrict__ degW,
         const float* __restrict__ bias,
         float*       __restrict__ out)
{
    __shared__ __align__(16) float fbuf[NBUF][CHK * 64];   // 4 x 8KB ring
    __shared__ int      rid_s[TM];
    __shared__ int      deg_s[TM];
    __shared__ int      edg_s[TM * D_];
    __shared__ unsigned pres_s;

    const int tid = threadIdx.x;
    if (tid == 0) pres_s = 0u;
    __syncthreads();

    // ---- map tile slots -> bucketed rows ----
    if (tid < TM) {
        int s = blockIdx.x * TM + tid;
        int accc = 0, d = 0, idx = 0;
        #pragma unroll
        for (int dd = 0; dd < 6; dd++) {
            int c = g_cnt[dd];
            if (s >= accc && s < accc + c) { d = dd; idx = s - accc; }
            accc += c;
        }
        int rid = g_lists[d][idx];
        rid_s[tid] = rid;
        deg_s[tid] = d;
        atomicOr(&pres_s, 1u << d);
        const int* e = edges + (size_t)rid * D_;
        #pragma unroll
        for (int j = 0; j < D_; j++) edg_s[tid * D_ + j] = e[j];
    }
    __syncthreads();

    const unsigned pres = pres_s;

    if (tid >= NCONS) {
        // ================= PRODUCER (warps 8-9) =================
        const int ptid = tid - NCONS;
        int gc = 0;                               // global chunk counter
        for (int d = 0; d < 6; d++) {
            if (!((pres >> d) & 1u)) continue;
            #pragma unroll 1
            for (int c = 0; c < NC; c++) {
                int s = gc & (NBUF - 1);
                if (gc >= NBUF) BAR_SYNC(5 + s);          // wait EMPTY
                build_chunk_prod(fbuf[s], c, ptid, atoms, bonds, rid_s, edg_s);
                BAR_ARRIVE(1 + s);                        // signal FULL
                gc++;
            }
        }
    } else {
        // ================= CONSUMER (warps 0-7) =================
        const int c4col = tid & 63;          // cols 4*c4col .. 4*c4col+3
        const int h     = tid >> 6;          // rows 16h .. 16h+15
        const float4 bo = ((const float4*)bias)[c4col];
        int gc = 0;

        for (int d = 0; d < 6; d++) {
            if (!((pres >> d) & 1u)) continue;

            const float* wbase = degW + (size_t)d * WSTRIDE + 4 * c4col;

            ull acc[8][4];
            #pragma unroll
            for (int q = 0; q < 8; q++)
                #pragma unroll
                for (int cc = 0; cc < 4; cc++) acc[q][cc] = 0ull;

            #pragma unroll 1
            for (int c = 0; c < NC; c++) {
                int s = gc & (NBUF - 1);
                BAR_SYNC(1 + s);                          // wait FULL
                const float* wk = wbase + (size_t)(c * CHK) * O_;
                if (c < 8) gemv_chunk<32>(fbuf[s], wk, h, acc);
                else       gemv_chunk<6>(fbuf[s], wk, h, acc);
                BAR_ARRIVE(5 + s);                        // signal EMPTY
                gc++;
            }

            // epilogue: rows r0 = 16h + 4*(q>>1) + 2*(q&1), r0+1
            #pragma unroll
            for (int q = 0; q < 8; q++) {
                int r0 = 16 * h + 4 * (q >> 1) + 2 * (q & 1);
                int r1 = r0 + 1;
                float lo[4], hi[4];
                #pragma unroll
                for (int cc = 0; cc < 4; cc++) {
                    asm("mov.b64 {%0, %1}, %2;" : "=f"(lo[cc]), "=f"(hi[cc]) : "l"(acc[q][cc]));
                }
                if (deg_s[r0] == d) {
                    float4 v = make_float4(sigf(lo[0] + bo.x), sigf(lo[1] + bo.y),
                                           sigf(lo[2] + bo.z), sigf(lo[3] + bo.w));
                    *(float4*)(out + (size_t)rid_s[r0] * O_ + 4 * c4col) = v;
                }
                if (deg_s[r1] == d) {
                    float4 v = make_float4(sigf(hi[0] + bo.x), sigf(hi[1] + bo.y),
                                           sigf(hi[2] + bo.z), sigf(hi[3] + bo.w));
                    *(float4*)(out + (size_t)rid_s[r1] * O_ + 4 * c4col) = v;
                }
            }
        }
    }

    // ---- self-resetting state for the next call ----
    __syncthreads();
    if (tid == 0) {
        int v = atomicAdd(&g_done, 1);
        if (v == NTILES - 1) {
            #pragma unroll
            for (int i = 0; i < 8; i++) g_cnt[i] = 0;
            g_done = 0;
            __threadfence();
        }
    }
}

extern "C" void kernel_launch(void* const* d_in, const int* in_sizes, int n_in,
                              void* d_out, int out_size) {
    const float* atoms = (const float*)d_in[0];
    const float* bonds = (const float*)d_in[1];
    const int*   edges = (const int*)d_in[2];
    const float* degW  = (const float*)d_in[3];
    const float* bvec  = (const float*)d_in[4];
    float* out = (float*)d_out;

    classify_kernel<<<ROWS_TOTAL / 256, 256>>>(edges);
    nfp_gemm<<<NTILES, NTHR>>>(atoms, bonds, edges, degW, bvec, out);
}

// round 14
// speedup vs baseline: 1.4156x; 1.4156x over previous
#include <cuda_runtime.h>
#include <cstdint>

#define B_   64
#define A_   1024
#define D_   5
#define F_   256
#define NB_  6
#define O_   256
#define K_   262
#define TM   64
#define NTHR 256
#define CHK  32
#define NC   9            // 8 atom chunks of 32 + 1 bonds chunk of 6
#define ROWS_TOTAL (B_ * A_)
#define NTILES (ROWS_TOTAL / TM)
#define WSTRIDE (K_ * O_)
#define FBUF_FLOATS (CHK * 64)      // 2048
#define WBUF_FLOATS (CHK * O_)      // 8192

typedef unsigned long long ull;

__device__ int g_cnt[8];          // statically zero; reset by last CTA each call
__device__ int g_done;
__device__ int g_lists[6][ROWS_TOTAL];

__device__ __forceinline__ ull pack2(float x) {
    ull r; asm("mov.b64 %0, {%1, %1};" : "=l"(r) : "f"(x)); return r;
}
__device__ __forceinline__ void fma2(ull& a, ull x, ull y) {
    asm("fma.rn.f32x2 %0, %1, %2, %0;" : "+l"(a) : "l"(x), "l"(y));
}
__device__ __forceinline__ float sigf(float z) {
    return __fdividef(1.f, 1.f + __expf(-z));
}
__device__ __forceinline__ uint32_t smem_u32(const void* p) {
    uint32_t a;
    asm("{ .reg .u64 t; cvta.to.shared.u64 t, %1; cvt.u32.u64 %0, t; }" : "=r"(a) : "l"(p));
    return a;
}
__device__ __forceinline__ void cpasync16(uint32_t dst, const float* src) {
    asm volatile("cp.async.cg.shared.global [%0], [%1], 16;" :: "r"(dst), "l"(src));
}
#define CPASYNC_COMMIT() asm volatile("cp.async.commit_group;" ::: "memory")
#define CPASYNC_WAIT0()  asm volatile("cp.async.wait_group 0;" ::: "memory")

__global__ void classify_kernel(const int* __restrict__ edges) {
    int rid = blockIdx.x * blockDim.x + threadIdx.x;
    const int* e = edges + (size_t)rid * D_;
    int d = 0;
    #pragma unroll
    for (int j = 0; j < D_; j++) d += (e[j] >= 0);
    unsigned lt = (1u << (threadIdx.x & 31)) - 1u;
    #pragma unroll
    for (int dd = 0; dd < 6; dd++) {
        unsigned m = __ballot_sync(0xffffffffu, d == dd);
        if (d == dd) {
            int leader = __ffs(m) - 1;
            int base = 0;
            if ((int)(threadIdx.x & 31) == leader) base = atomicAdd(&g_cnt[dd], __popc(m));
            base = __shfl_sync(m, base, leader);
            g_lists[dd][base + __popc(m & lt)] = rid;
        }
    }
}

// ---- async stage one chunk's weights (contiguous nk*256 floats) into smem ----
__device__ __forceinline__ void wload_issue(uint32_t wdst, const float* __restrict__ wk, int nk) {
    const int tid = threadIdx.x;
    const int njobs = nk * 64;                    // 16B jobs (2048 for CHK, 384 for bonds)
    for (int idx = tid; idx < njobs; idx += NTHR)
        cpasync16(wdst + idx * 16, wk + idx * 4);
    CPASYNC_COMMIT();
}

// ---- build one chunk of the transposed feats tile (swizzled, conflict-free) ----
__device__ __forceinline__ void build_chunk(float* __restrict__ dst, int c,
                                            const float* __restrict__ atoms,
                                            const float* __restrict__ bonds,
                                            const int* __restrict__ rid_s,
                                            const int* __restrict__ edg_s) {
    const int tid = threadIdx.x;
    if (c < 8) {
        const float4* a4 = (const float4*)atoms;
        #pragma unroll
        for (int it = 0; it < 2; it++) {
            int job = it * NTHR + tid;
            int r = job >> 3, c4 = job & 7;     // r 0..63, c4 0..7 (k' = 4c4..4c4+3)
            int rid = rid_s[r];
            int cg = c * 8 + c4;
            float4 v = a4[(size_t)rid * 64 + cg];
            int bbase = rid & ~(A_ - 1);
            #pragma unroll
            for (int j = 0; j < D_; j++) {
                int e = edg_s[r * D_ + j];
                if (e >= 0) {
                    float4 n = a4[(size_t)(bbase + e) * 64 + cg];
                    v.x += n.x; v.y += n.y; v.z += n.z; v.w += n.w;
                }
            }
            int p = (r >> 2) ^ c4;
            float* b = dst + (4 * c4) * 64 + 4 * p + (r & 3);
            b[0 * 64] = v.x;
            b[1 * 64] = v.y;
            b[2 * 64] = v.z;
            b[3 * 64] = v.w;
        }
    } else {
        #pragma unroll
        for (int it = 0; it < 2; it++) {
            int job = it * NTHR + tid;
            int r = job >> 3, c4 = job & 7;
            if (c4 < 2) {
                const float* bb = bonds + (size_t)rid_s[r] * (D_ * NB_);
                #pragma unroll
                for (int q = 0; q < 4; q++) {
                    int nb = 4 * c4 + q;
                    if (nb < NB_) {
                        float s = 0.f;
                        #pragma unroll
                        for (int j = 0; j < D_; j++) s += bb[j * NB_ + nb];
                        int p = (r >> 2) ^ (nb >> 2);
                        dst[nb * 64 + 4 * p + (r & 3)] = s;
                    }
                }
            }
        }
    }
}

// ---- GEMV over one chunk: 16 rows x 4 cols per thread; weights from smem ----
template <int NK>
__device__ __forceinline__ void gemv_chunk(const float* __restrict__ fb,
                                           const float* __restrict__ wsm,  // wbuf + 4*c4col
                                           int h, ull acc[8][4]) {
    #pragma unroll
    for (int k4 = 0; k4 < (NK + 3) / 4; k4++) {
        const int sk = k4;
        int of0 = 4 * ((4 * h + 0) ^ sk);
        int of1 = 4 * ((4 * h + 1) ^ sk);
        int of2 = 4 * ((4 * h + 2) ^ sk);
        int of3 = 4 * ((4 * h + 3) ^ sk);
        const float* f0 = fb + k4 * 4 * 64;
        const int jmax = (NK - 4 * k4 < 4) ? (NK - 4 * k4) : 4;
        #pragma unroll
        for (int j = 0; j < jmax; j++) {
            float4 w = *(const float4*)(wsm + (size_t)(4 * k4 + j) * O_);
            ull wx = pack2(w.x), wy = pack2(w.y), wz = pack2(w.z), ww = pack2(w.w);
            const float* fj = f0 + j * 64;
            ulonglong2 fa = *(const ulonglong2*)(fj + of0);
            ulonglong2 fb2 = *(const ulonglong2*)(fj + of1);
            ulonglong2 fc = *(const ulonglong2*)(fj + of2);
            ulonglong2 fd = *(const ulonglong2*)(fj + of3);
            fma2(acc[0][0], fa.x, wx); fma2(acc[0][1], fa.x, wy); fma2(acc[0][2], fa.x, wz); fma2(acc[0][3], fa.x, ww);
            fma2(acc[1][0], fa.y, wx); fma2(acc[1][1], fa.y, wy); fma2(acc[1][2], fa.y, wz); fma2(acc[1][3], fa.y, ww);
            fma2(acc[2][0], fb2.x, wx); fma2(acc[2][1], fb2.x, wy); fma2(acc[2][2], fb2.x, wz); fma2(acc[2][3], fb2.x, ww);
            fma2(acc[3][0], fb2.y, wx); fma2(acc[3][1], fb2.y, wy); fma2(acc[3][2], fb2.y, wz); fma2(acc[3][3], fb2.y, ww);
            fma2(acc[4][0], fc.x, wx); fma2(acc[4][1], fc.x, wy); fma2(acc[4][2], fc.x, wz); fma2(acc[4][3], fc.x, ww);
            fma2(acc[5][0], fc.y, wx); fma2(acc[5][1], fc.y, wy); fma2(acc[5][2], fc.y, wz); fma2(acc[5][3], fc.y, ww);
            fma2(acc[6][0], fd.x, wx); fma2(acc[6][1], fd.x, wy); fma2(acc[6][2], fd.x, wz); fma2(acc[6][3], fd.x, ww);
            fma2(acc[7][0], fd.y, wx); fma2(acc[7][1], fd.y, wy); fma2(acc[7][2], fd.y, wz); fma2(acc[7][3], fd.y, ww);
        }
    }
}

extern __shared__ float dsm[];   // [0,4096) fbuf0/1 | [4096,20480) wbuf0/1  (80 KB)

__global__ void __launch_bounds__(NTHR, 2)
nfp_gemm(const float* __restrict__ atoms,
         const float* __restrict__ bonds,
         const int*   __restrict__ edges,
         const float* __restrict__ degW,
         const float* __restrict__ bias,
         float*       __restrict__ out)
{
    __shared__ int      rid_s[TM];
    __shared__ int      deg_s[TM];
    __shared__ int      edg_s[TM * D_];
    __shared__ unsigned pres_s;

    float* fbuf[2] = { dsm, dsm + FBUF_FLOATS };
    float* wbuf[2] = { dsm + 2 * FBUF_FLOATS, dsm + 2 * FBUF_FLOATS + WBUF_FLOATS };
    const uint32_t wbuf_u32[2] = { smem_u32(wbuf[0]), smem_u32(wbuf[1]) };

    const int tid = threadIdx.x;
    if (tid == 0) pres_s = 0u;
    __syncthreads();

    // ---- map tile slots -> bucketed rows ----
    if (tid < TM) {
        int s = blockIdx.x * TM + tid;
        int accc = 0, d = 0, idx = 0;
        #pragma unroll
        for (int dd = 0; dd < 6; dd++) {
            int c = g_cnt[dd];
            if (s >= accc && s < accc + c) { d = dd; idx = s - accc; }
            accc += c;
        }
        int rid = g_lists[d][idx];
        rid_s[tid] = rid;
        deg_s[tid] = d;
        atomicOr(&pres_s, 1u << d);
        const int* e = edges + (size_t)rid * D_;
        #pragma unroll
        for (int j = 0; j < D_; j++) edg_s[tid * D_ + j] = e[j];
    }
    __syncthreads();

    const int c4col = tid & 63;          // cols 4*c4col .. 4*c4col+3
    const int h     = tid >> 6;          // rows 16h .. 16h+15
    const float4 bo = ((const float4*)bias)[c4col];
    const unsigned pres = pres_s;

    for (int d = 0; d < 6; d++) {
        if (!((pres >> d) & 1u)) continue;       // uniform branch

        const float* wbase = degW + (size_t)d * WSTRIDE;

        ull acc[8][4];
        #pragma unroll
        for (int q = 0; q < 8; q++)
            #pragma unroll
            for (int cc = 0; cc < 4; cc++) acc[q][cc] = 0ull;

        // prologue: stage weights(0) async; build feats(0) under the copy latency
        wload_issue(wbuf_u32[0], wbase, CHK);
        build_chunk(fbuf[0], 0, atoms, bonds, rid_s, edg_s);
        CPASYNC_WAIT0();
        __syncthreads();

        #pragma unroll 1
        for (int c = 0; c < NC; c++) {
            // 1) stage next chunk's weights (async, zero-register)
            if (c + 1 < NC)
                wload_issue(wbuf_u32[(c + 1) & 1],
                            wbase + (size_t)(c + 1) * CHK * O_,
                            (c + 1 < 8) ? CHK : NB_);
            // 2) GEMV on current chunk (weights + feats from smem)
            if (c < 8) gemv_chunk<CHK>(fbuf[c & 1], wbuf[c & 1] + 4 * c4col, h, acc);
            else       gemv_chunk<NB_>(fbuf[c & 1], wbuf[c & 1] + 4 * c4col, h, acc);
            // 3) build next feats chunk; then drain the weight copy (long landed)
            if (c + 1 < NC) {
                build_chunk(fbuf[(c + 1) & 1], c + 1, atoms, bonds, rid_s, edg_s);
                CPASYNC_WAIT0();
            }
            __syncthreads();
        }

        // epilogue: rows r0 = 16h + 4*(q>>1) + 2*(q&1), r0+1
        #pragma unroll
        for (int q = 0; q < 8; q++) {
            int r0 = 16 * h + 4 * (q >> 1) + 2 * (q & 1);
            int r1 = r0 + 1;
            float lo[4], hi[4];
            #pragma unroll
            for (int cc = 0; cc < 4; cc++) {
                asm("mov.b64 {%0, %1}, %2;" : "=f"(lo[cc]), "=f"(hi[cc]) : "l"(acc[q][cc]));
            }
            if (deg_s[r0] == d) {
                float4 v = make_float4(sigf(lo[0] + bo.x), sigf(lo[1] + bo.y),
                                       sigf(lo[2] + bo.z), sigf(lo[3] + bo.w));
                *(float4*)(out + (size_t)rid_s[r0] * O_ + 4 * c4col) = v;
            }
            if (deg_s[r1] == d) {
                float4 v = make_float4(sigf(hi[0] + bo.x), sigf(hi[1] + bo.y),
                                       sigf(hi[2] + bo.z), sigf(hi[3] + bo.w));
                *(float4*)(out + (size_t)rid_s[r1] * O_ + 4 * c4col) = v;
            }
        }
    }

    // ---- self-resetting state for the next call ----
    __syncthreads();
    if (tid == 0) {
        int v = atomicAdd(&g_done, 1);
        if (v == NTILES - 1) {
            #pragma unroll
            for (int i = 0; i < 8; i++) g_cnt[i] = 0;
            g_done = 0;
            __threadfence();
        }
    }
}

extern "C" void kernel_launch(void* const* d_in, const int* in_sizes, int n_in,
                              void* d_out, int out_size) {
    const float* atoms = (const float*)d_in[0];
    const float* bonds = (const float*)d_in[1];
    const int*   edges = (const int*)d_in[2];
    const float* degW  = (const float*)d_in[3];
    const float* bvec  = (const float*)d_in[4];
    float* out = (float*)d_out;

    const int dsm_bytes = (2 * FBUF_FLOATS + 2 * WBUF_FLOATS) * sizeof(float);  // 80 KB
    cudaFuncSetAttribute(nfp_gemm, cudaFuncAttributeMaxDynamicSharedMemorySize, dsm_bytes);

    classify_kernel<<<ROWS_TOTAL / 256, 256>>>(edges);
    nfp_gemm<<<NTILES, NTHR, dsm_bytes>>>(atoms, bonds, edges, degW, bvec, out);
}

// round 15
// speedup vs baseline: 1.4309x; 1.0108x over previous
#include <cuda_runtime.h>
#include <cstdint>

#define B_   64
#define A_   1024
#define D_   5
#define F_   256
#define NB_  6
#define O_   256
#define K_   262
#define TM   64
#define NTHR 256
#define CHK  64
#define NC   5            // 4 atom chunks of 64 + 1 bonds chunk of 6
#define ROWS_TOTAL (B_ * A_)
#define NTILES (ROWS_TOTAL / TM)
#define WSTRIDE (K_ * O_)

typedef unsigned long long ull;

__device__ int g_cnt[8];          // statically zero; reset by last CTA each call
__device__ int g_done;
__device__ int g_lists[6][ROWS_TOTAL];

__device__ __forceinline__ ull pack2(float x) {
    ull r; asm("mov.b64 %0, {%1, %1};" : "=l"(r) : "f"(x)); return r;
}
__device__ __forceinline__ void fma2(ull& a, ull x, ull y) {
    asm("fma.rn.f32x2 %0, %1, %2, %0;" : "+l"(a) : "l"(x), "l"(y));
}
__device__ __forceinline__ float sigf(float z) {
    return __fdividef(1.f, 1.f + __expf(-z));
}

__global__ void classify_kernel(const int* __restrict__ edges) {
    int rid = blockIdx.x * blockDim.x + threadIdx.x;
    const int* e = edges + (size_t)rid * D_;
    int d = 0;
    #pragma unroll
    for (int j = 0; j < D_; j++) d += (e[j] >= 0);
    unsigned lt = (1u << (threadIdx.x & 31)) - 1u;
    #pragma unroll
    for (int dd = 0; dd < 6; dd++) {
        unsigned m = __ballot_sync(0xffffffffu, d == dd);
        if (d == dd) {
            int leader = __ffs(m) - 1;
            int base = 0;
            if ((int)(threadIdx.x & 31) == leader) base = atomicAdd(&g_cnt[dd], __popc(m));
            base = __shfl_sync(m, base, leader);
            g_lists[dd][base + __popc(m & lt)] = rid;
        }
    }
}

// ---- build one 64-k chunk of the transposed feats tile (swizzled) ----
// 1024 jobs: r = job>>4 (0..63), c4 = job&15 (float4 col within chunk)
__device__ __forceinline__ void build_chunk(float* __restrict__ dst, int c,
                                            const float* __restrict__ atoms,
                                            const float* __restrict__ bonds,
                                            const int* __restrict__ rid_s,
                                            const int* __restrict__ edg_s) {
    const int tid = threadIdx.x;
    if (c < 4) {
        const float4* a4 = (const float4*)atoms;
        #pragma unroll
        for (int it = 0; it < 4; it++) {
            int job = it * NTHR + tid;
            int r = job >> 4, c4 = job & 15;
            int rid = rid_s[r];
            int cg = c * 16 + c4;
            float4 v = a4[(size_t)rid * 64 + cg];
            int bbase = rid & ~(A_ - 1);
            #pragma unroll
            for (int j = 0; j < D_; j++) {
                int e = edg_s[r * D_ + j];
                if (e >= 0) {
                    float4 n = a4[(size_t)(bbase + e) * 64 + cg];
                    v.x += n.x; v.y += n.y; v.z += n.z; v.w += n.w;
                }
            }
            int p = (r >> 2) ^ c4;                 // 0..15
            float* b = dst + (4 * c4) * 64 + 4 * p + (r & 3);
            b[0 * 64] = v.x;
            b[1 * 64] = v.y;
            b[2 * 64] = v.z;
            b[3 * 64] = v.w;
        }
    } else {
        // bonds chunk: k' = nb in [0,6)
        #pragma unroll
        for (int it = 0; it < 2; it++) {
            int job = it * NTHR + tid;
            int r = job >> 3, c4 = job & 7;
            if (c4 < 2) {
                const float* bb = bonds + (size_t)rid_s[r] * (D_ * NB_);
                #pragma unroll
                for (int q = 0; q < 4; q++) {
                    int nb = 4 * c4 + q;
                    if (nb < NB_) {
                        float s = 0.f;
                        #pragma unroll
                        for (int j = 0; j < D_; j++) s += bb[j * NB_ + nb];
                        int p = (r >> 2) ^ (nb >> 2);
                        dst[nb * 64 + 4 * p + (r & 3)] = s;
                    }
                }
            }
        }
    }
}

// ---- GEMV over one chunk: 16 rows x 4 cols per thread; rolled k4 loop ----
template <int NK>
__device__ __forceinline__ void gemv_chunk(const float* __restrict__ fb,
                                           const float* __restrict__ wk,
                                           int h, ull acc[8][4]) {
    #pragma unroll 1
    for (int k4 = 0; k4 < (NK + 3) / 4; k4++) {
        const int sk = k4;
        int of0 = 4 * ((4 * h + 0) ^ sk);
        int of1 = 4 * ((4 * h + 1) ^ sk);
        int of2 = 4 * ((4 * h + 2) ^ sk);
        int of3 = 4 * ((4 * h + 3) ^ sk);
        const float* f0 = fb + k4 * 4 * 64;
        const int jmax = (NK - 4 * k4 < 4) ? (NK - 4 * k4) : 4;
        #pragma unroll
        for (int j = 0; j < 4; j++) {
            if (j >= jmax) break;
            float4 w = *(const float4*)(wk + (size_t)(4 * k4 + j) * O_);
            ull wx = pack2(w.x), wy = pack2(w.y), wz = pack2(w.z), ww = pack2(w.w);
            const float* fj = f0 + j * 64;
            ulonglong2 fa = *(const ulonglong2*)(fj + of0);
            ulonglong2 fb2 = *(const ulonglong2*)(fj + of1);
            ulonglong2 fc = *(const ulonglong2*)(fj + of2);
            ulonglong2 fd = *(const ulonglong2*)(fj + of3);
            fma2(acc[0][0], fa.x, wx); fma2(acc[0][1], fa.x, wy); fma2(acc[0][2], fa.x, wz); fma2(acc[0][3], fa.x, ww);
            fma2(acc[1][0], fa.y, wx); fma2(acc[1][1], fa.y, wy); fma2(acc[1][2], fa.y, wz); fma2(acc[1][3], fa.y, ww);
            fma2(acc[2][0], fb2.x, wx); fma2(acc[2][1], fb2.x, wy); fma2(acc[2][2], fb2.x, wz); fma2(acc[2][3], fb2.x, ww);
            fma2(acc[3][0], fb2.y, wx); fma2(acc[3][1], fb2.y, wy); fma2(acc[3][2], fb2.y, wz); fma2(acc[3][3], fb2.y, ww);
            fma2(acc[4][0], fc.x, wx); fma2(acc[4][1], fc.x, wy); fma2(acc[4][2], fc.x, wz); fma2(acc[4][3], fc.x, ww);
            fma2(acc[5][0], fc.y, wx); fma2(acc[5][1], fc.y, wy); fma2(acc[5][2], fc.y, wz); fma2(acc[5][3], fc.y, ww);
            fma2(acc[6][0], fd.x, wx); fma2(acc[6][1], fd.x, wy); fma2(acc[6][2], fd.x, wz); fma2(acc[6][3], fd.x, ww);
            fma2(acc[7][0], fd.y, wx); fma2(acc[7][1], fd.y, wy); fma2(acc[7][2], fd.y, wz); fma2(acc[7][3], fd.y, ww);
        }
    }
}

__global__ void __launch_bounds__(NTHR, 2)
nfp_gemm(const float* __restrict__ atoms,
         const float* __restrict__ bonds,
         const int*   __restrict__ edges,
         const float* __restrict__ degW,
         const float* __restrict__ bias,
         float*       __restrict__ out)
{
    __shared__ __align__(16) float fbuf[2][CHK * 64];   // 2 x 16KB
    __shared__ int      rid_s[TM];
    __shared__ int      deg_s[TM];
    __shared__ int      edg_s[TM * D_];
    __shared__ unsigned pres_s;

    const int tid = threadIdx.x;
    if (tid == 0) pres_s = 0u;
    __syncthreads();

    // ---- map tile slots -> bucketed rows ----
    if (tid < TM) {
        int s = blockIdx.x * TM + tid;
        int accc = 0, d = 0, idx = 0;
        #pragma unroll
        for (int dd = 0; dd < 6; dd++) {
            int c = g_cnt[dd];
            if (s >= accc && s < accc + c) { d = dd; idx = s - accc; }
            accc += c;
        }
        int rid = g_lists[d][idx];
        rid_s[tid] = rid;
        deg_s[tid] = d;
        atomicOr(&pres_s, 1u << d);
        const int* e = edges + (size_t)rid * D_;
        #pragma unroll
        for (int j = 0; j < D_; j++) edg_s[tid * D_ + j] = e[j];
    }
    __syncthreads();

    const int c4col = tid & 63;          // cols 4*c4col .. 4*c4col+3
    const int h     = tid >> 6;          // rows 16h .. 16h+15
    const float4 bo = ((const float4*)bias)[c4col];
    const unsigned pres = pres_s;

    for (int d = 0; d < 6; d++) {
        if (!((pres >> d) & 1u)) continue;       // uniform branch

        const float* wbase = degW + (size_t)d * WSTRIDE + 4 * c4col;

        ull acc[8][4];
        #pragma unroll
        for (int q = 0; q < 8; q++)
            #pragma unroll
            for (int cc = 0; cc < 4; cc++) acc[q][cc] = 0ull;

        build_chunk(fbuf[0], 0, atoms, bonds, rid_s, edg_s);
        __syncthreads();

        #pragma unroll 1
        for (int c = 0; c < NC; c++) {
            if (c + 1 < NC)
                build_chunk(fbuf[(c + 1) & 1], c + 1, atoms, bonds, rid_s, edg_s);
            const float* wk = wbase + (size_t)(c * CHK) * O_;
            if (c < 4) gemv_chunk<CHK>(fbuf[c & 1], wk, h, acc);
            else       gemv_chunk<NB_>(fbuf[c & 1], wk, h, acc);
            __syncthreads();
        }

        // epilogue: rows r0 = 16h + 4*(q>>1) + 2*(q&1), r0+1
        #pragma unroll
        for (int q = 0; q < 8; q++) {
            int r0 = 16 * h + 4 * (q >> 1) + 2 * (q & 1);
            int r1 = r0 + 1;
            float lo[4], hi[4];
            #pragma unroll
            for (int cc = 0; cc < 4; cc++) {
                asm("mov.b64 {%0, %1}, %2;" : "=f"(lo[cc]), "=f"(hi[cc]) : "l"(acc[q][cc]));
            }
            if (deg_s[r0] == d) {
                float4 v = make_float4(sigf(lo[0] + bo.x), sigf(lo[1] + bo.y),
                                       sigf(lo[2] + bo.z), sigf(lo[3] + bo.w));
                *(float4*)(out + (size_t)rid_s[r0] * O_ + 4 * c4col) = v;
            }
            if (deg_s[r1] == d) {
                float4 v = make_float4(sigf(hi[0] + bo.x), sigf(hi[1] + bo.y),
                                       sigf(hi[2] + bo.z), sigf(hi[3] + bo.w));
                *(float4*)(out + (size_t)rid_s[r1] * O_ + 4 * c4col) = v;
            }
        }
    }

    // ---- self-resetting state for the next call ----
    __syncthreads();
    if (tid == 0) {
        int v = atomicAdd(&g_done, 1);
        if (v == NTILES - 1) {
            #pragma unroll
            for (int i = 0; i < 8; i++) g_cnt[i] = 0;
            g_done = 0;
            __threadfence();
        }
    }
}

extern "C" void kernel_launch(void* const* d_in, const int* in_sizes, int n_in,
                              void* d_out, int out_size) {
    const float* atoms = (const float*)d_in[0];
    const float* bonds = (const float*)d_in[1];
    const int*   edges = (const int*)d_in[2];
    const float* degW  = (const float*)d_in[3];
    const float* bvec  = (const float*)d_in[4];
    float* out = (float*)d_out;

    classify_kernel<<<ROWS_TOTAL / 256, 256>>>(edges);
    nfp_gemm<<<NTILES, NTHR>>>(atoms, bonds, edges, degW, bvec, out);
}